// round 8
// baseline (speedup 1.0000x reference)
#include <cuda_runtime.h>
#include <math.h>

#define BB 16
#define AA 3
#define CC 80
#define HH 76
#define WW 76
#define TT 50
#define PLANE (HH*WW)            // 5776
#define NPLANES (BB*AA)          // 48 conf planes
#define NT (BB*TT)               // 800 targets
#define CONF_BLOCKS (NPLANES*2)  // 96 (half-plane per block)
#define TGT_BLOCKS 50            // 16 warps each -> exactly 800 warps
#define DEDUPE_BLOCK (CONF_BLOCKS + TGT_BLOCKS)      // 146
#define GRID (CONF_BLOCKS + TGT_BLOCKS + 1)          // 147 blocks, one wave
#define NTHREADS 512
#define HALFQ 722                // float4 per half-plane
#define NBITWORDS ((NPLANES*PLANE + 31)/32)          // 8664 words = 34.7KB
#define NSLOT 16
#define SLOT_STRIDE 64           // 64 floats = 256B apart -> distinct L2 slices

__constant__ float c_anch[18] = {10.f,13.f,16.f,30.f,33.f,23.f,30.f,61.f,62.f,45.f,
                                 59.f,119.f,116.f,90.f,156.f,198.f,373.f,326.f};

__device__ float g_slot[NSLOT * SLOT_STRIDE];   // zero at load; reset by tail
__device__ int   g_done = 0;                    // completion counter

// fast sigmoid: MUFU.EX2 + MUFU.RCP  (rel err ~1e-6, tolerance 1e-3)
__device__ __forceinline__ float sigf(float z) {
    return __fdividef(1.f, 1.f + __expf(-z));
}
// BCE on logits: -log(sig(v)) = softplus(-v); -log1p(-sig(v)) = softplus(v)
__device__ __forceinline__ float softplus(float x) {
    return __logf(1.f + __expf(x));
}

__device__ __forceinline__ void anchor_match(float tw, float th, int& bi) {
    float best = -1e30f; bi = 0;
    #pragma unroll
    for (int k = 0; k < 9; k++) {
        float aw = c_anch[2 * k]     * (1.f / 608.f);
        float ah = c_anch[2 * k + 1] * (1.f / 608.f);
        float inter = fminf(tw, aw) * fminf(th, ah);
        float uni   = tw * th + aw * ah - inter;
        float iou   = __fdividef(inter, uni);
        if (iou > best) { best = iou; bi = k; }
    }
}

__global__ void __launch_bounds__(NTHREADS, 1)
fused_kernel(const float* __restrict__ in,
             const float* __restrict__ tgt,
             float* __restrict__ out) {
    __shared__ unsigned bm[NBITWORDS];   // used by dedupe block only
    __shared__ int s_islast;
    __shared__ int s_va;

    int tid = threadIdx.x;
    int l = tid & 31;
    int bid = blockIdx.x;
    float* slot = &g_slot[(bid & (NSLOT - 1)) * SLOT_STRIDE];

    // ───────────── phase A ─────────────
    if (bid < CONF_BLOCKS) {
        // half-plane sigmoid reduction: 2 explicit loads, MLP=2
        int plane = bid >> 1, half = bid & 1;
        int b = plane / AA, a = plane - b * AA;
        const float4* p = (const float4*)(in + (size_t)(b * 255 + a * 85 + 4) * PLANE)
                        + half * HALFQ;
        float4 v0 = p[tid];                    // tid < 722 always
        float4 v1;
        bool has1 = (tid + NTHREADS) < HALFQ;  // tid < 210
        if (has1) v1 = p[tid + NTHREADS];
        float s = sigf(v0.x) + sigf(v0.y) + sigf(v0.z) + sigf(v0.w);
        if (has1) s += sigf(v1.x) + sigf(v1.y) + sigf(v1.z) + sigf(v1.w);

        for (int o = 16; o > 0; o >>= 1) s += __shfl_down_sync(0xffffffffu, s, o);
        if (l == 0) atomicAdd(slot, s);        // RED.ADD.F32 (spread addresses)
    } else if (bid < DEDUPE_BLOCK) {
        // target blocks: one warp per target, 16 targets/block
        // step 1: block-local num_truths over ALL 800 targets (L2-hot 16KB)
        if (tid == 0) s_va = 0;
        __syncthreads();
        {
            int va = 0;
            for (int t = tid; t < NT; t += NTHREADS) {
                const float* t5 = tgt + t * 5;  // contiguous: b*(TT*5)+(t%TT)*5 == t*5
                va += ((t5[0] + t5[1] + t5[2] + t5[3] + t5[4]) != 0.f);
            }
            for (int o = 16; o > 0; o >>= 1) va += __shfl_down_sync(0xffffffffu, va, o);
            if (l == 0 && va) atomicAdd(&s_va, va);
        }
        __syncthreads();
        float inv_nt = __fdividef(1.f, fmaxf((float)s_va, 1.f));

        // step 2: per-warp gather + loss
        int t = (bid - CONF_BLOCKS) * 16 + (tid >> 5);
        const float* t5 = tgt + t * 5;
        float tc = t5[0], tx = t5[1], ty = t5[2], tw = t5[3], th = t5[4];
        int valid = ((tc + tx + ty + tw + th) != 0.f);

        int bi; anchor_match(tw, th, bi);
        if (valid && (bi < AA)) {
            int a_n = bi;
            int gi = (int)(tx * (float)WW); gi = min(max(gi, 0), WW - 1);
            int gj = (int)(ty * (float)HH); gj = min(max(gj, 0), HH - 1);
            int pos = gj * WW + gi;

            float aw_s = c_anch[2 * a_n], ah_s = c_anch[2 * a_n + 1];
            float tx_t = tx * (float)WW - (float)gi;
            float ty_t = ty * (float)HH - (float)gj;
            float tw_t = __logf(tw * 608.f / aw_s);
            float th_t = __logf(th * 608.f / ah_s);
            float scale = 2.f * ty * tw;      // faithful to reference quirk
            int ci = (int)tc;

            const float* base = in + (size_t)((t / TT) * 255 + a_n * 85) * PLANE + pos;

            // lanes split the 85 channels (skip conf ch 4); all loads first, MLP=3
            float v0 = base[(size_t)l * PLANE];
            float v1 = base[(size_t)(l + 32) * PLANE];
            float v2 = (l + 64 < 85) ? base[(size_t)(l + 64) * PLANE] : 0.f;

            float acc_xy = 0.f, acc_cls = 0.f;
            if (l == 0)      acc_xy += scale * fabsf(sigf(v0) - tx_t);
            else if (l == 1) acc_xy += scale * fabsf(sigf(v0) - ty_t);
            else if (l == 2) acc_xy += scale * fabsf(v0 - tw_t);
            else if (l == 3) acc_xy += scale * fabsf(v0 - th_t);
            else if (l != 4) acc_cls += softplus((l - 5 == ci) ? -v0 : v0);
            acc_cls += softplus((l + 27 == ci) ? -v1 : v1);
            if (l + 64 < 85) acc_cls += softplus((l + 59 == ci) ? -v2 : v2);

            float acc = acc_cls + acc_xy * inv_nt;   // fold /num_truths per-warp
            for (int o = 16; o > 0; o >>= 1)
                acc += __shfl_down_sync(0xffffffffu, acc, o);
            if (l == 0) atomicAdd(slot, acc);        // ONE REDG per warp
        }
    } else {
        // dedupe block: depends ONLY on tgt (pure ALU + 16KB reads)
        for (int i = tid; i < NBITWORDS; i += NTHREADS) bm[i] = 0u;
        __syncthreads();

        for (int t = tid; t < NT; t += NTHREADS) {
            const float* t5 = tgt + t * 5;
            float tc = t5[0], tx = t5[1], ty = t5[2], tw = t5[3], th = t5[4];
            int valid = ((tc + tx + ty + tw + th) != 0.f);
            int bi; anchor_match(tw, th, bi);
            if (valid && bi < AA) {
                int b = t / TT;
                int gi = (int)(tx * (float)WW); gi = min(max(gi, 0), WW - 1);
                int gj = (int)(ty * (float)HH); gj = min(max(gj, 0), HH - 1);
                int cell = ((b * AA + bi) * HH + gj) * WW + gi;
                atomicOr(&bm[cell >> 5], 1u << (cell & 31));
            }
        }
        __syncthreads();
        int un = 0;
        for (int i = tid; i < NBITWORDS; i += NTHREADS) un += __popc(bm[i]);
        for (int o = 16; o > 0; o >>= 1) un += __shfl_down_sync(0xffffffffu, un, o);
        if (l == 0 && un) atomicAdd(slot, -(float)un);   // fold -unique here
    }

    // ───────────── completion protocol ─────────────
    __syncthreads();                          // all warps' REDGs issued
    if (tid == 0) {
        __threadfence();                      // publish this block's global writes
        int old = atomicAdd(&g_done, 1);
        s_islast = (old == GRID - 1);
    }
    __syncthreads();
    if (!s_islast) return;

    // ───────────── tail (last block, warp 0): 16 loads + shfl sum + store ───
    if (tid < 32) {
        if (tid == 0) __threadfence();        // acquire side
        __syncwarp();
        float v = (tid < NSLOT) ? g_slot[tid * SLOT_STRIDE] : 0.f;
        for (int o = 16; o > 0; o >>= 1) v += __shfl_down_sync(0xffffffffu, v, o);
        if (tid == 0) out[0] = v;
        // reset for next graph replay (same threads, after their reads)
        if (tid < NSLOT) g_slot[tid * SLOT_STRIDE] = 0.f;
        if (tid == 0) g_done = 0;
    }
}

extern "C" void kernel_launch(void* const* d_in, const int* in_sizes, int n_in,
                              void* d_out, int out_size) {
    const float* in  = (const float*)d_in[0];   // [16, 255, 76, 76]
    const float* tgt = (const float*)d_in[1];   // [16, 250]
    float* out = (float*)d_out;
    fused_kernel<<<GRID, NTHREADS>>>(in, tgt, out);
}